// round 2
// baseline (speedup 1.0000x reference)
#include <cuda_runtime.h>
#include <math.h>

#define H 1024
#define W 1024
#define BATCH 16
#define CH 3
#define NPLANE (H * W)
#define NPIX (BATCH * NPLANE)   /* 16,777,216 */

#define G0 0.13533528323661270f  /* exp(-2)   */
#define G1 0.60653065971263342f  /* exp(-0.5) */

/* ------------------------------------------------------------------ */
/* Kernel 1: fused separable 5x5 Gaussian blur (per plane)            */
/* tile 128x32 outputs, 256 threads                                   */
/* ------------------------------------------------------------------ */
#define BX 128
#define BY 32

__global__ __launch_bounds__(256) void blur_kernel(
    const float* __restrict__ img,
    const float* __restrict__ bh_p,
    const float* __restrict__ bv_p,
    float* __restrict__ out)
{
    __shared__ float s_in[BY + 4][BX + 4];
    __shared__ float s_h[BY + 4][BX];

    const float bh = __ldg(bh_p);
    const float bv = __ldg(bv_p);

    const int plane = blockIdx.z;                   /* 0..47 */
    const int x0 = blockIdx.x * BX;
    const int y0 = blockIdx.y * BY;
    const float* src = img + (size_t)plane * NPLANE;
    float* dst = out + (size_t)plane * NPLANE;
    const int tid = threadIdx.x;

    /* load input tile with 2-wide halo, zero OOB */
    #pragma unroll
    for (int idx = tid; idx < (BY + 4) * (BX + 4); idx += 256) {
        int r = idx / (BX + 4), c = idx % (BX + 4);
        int gy = y0 + r - 2, gx = x0 + c - 2;
        float v = 0.0f;
        if (gy >= 0 && gy < H && gx >= 0 && gx < W) v = src[gy * W + gx];
        s_in[r][c] = v;
    }
    __syncthreads();

    /* horizontal pass: +bh on every in-range row; OOB rows must stay 0 */
    #pragma unroll
    for (int idx = tid; idx < (BY + 4) * BX; idx += 256) {
        int r = idx / BX, c = idx % BX;
        int gy = y0 + r - 2;
        float v = 0.0f;
        if (gy >= 0 && gy < H) {
            v = G0 * (s_in[r][c] + s_in[r][c + 4])
              + G1 * (s_in[r][c + 1] + s_in[r][c + 3])
              + s_in[r][c + 2] + bh;
        }
        s_h[r][c] = v;
    }
    __syncthreads();

    /* vertical pass + bv, write out */
    #pragma unroll
    for (int idx = tid; idx < BY * BX; idx += 256) {
        int r = idx / BX, c = idx % BX;
        float v = G0 * (s_h[r][c] + s_h[r + 4][c])
                + G1 * (s_h[r + 1][c] + s_h[r + 3][c])
                + s_h[r + 2][c] + bv;
        dst[(size_t)(y0 + r) * W + x0 + c] = v;
    }
}

/* ------------------------------------------------------------------ */
/* Kernel 2: Sobel per channel -> mag sum, orientation, early thresh  */
/* block 32x16, one pixel per thread, channel-looped smem tile        */
/* ------------------------------------------------------------------ */
#define SBX 32
#define SBY 16

__global__ __launch_bounds__(512) void sobel_kernel(
    const float* __restrict__ blurred,
    const float* __restrict__ shb_p,
    const float* __restrict__ svb_p,
    float* __restrict__ gm_out,
    float* __restrict__ orient_out,
    float* __restrict__ early_out)
{
    __shared__ float s[SBY + 2][SBX + 2 + 1];

    const float shb = __ldg(shb_p);
    const float svb = __ldg(svb_p);

    const int b = blockIdx.z;
    const int x0 = blockIdx.x * SBX;
    const int y0 = blockIdx.y * SBY;
    const int tx = threadIdx.x, ty = threadIdx.y;
    const int tlin = ty * SBX + tx;

    float mag = 0.0f, sgx = 0.0f, sgy = 0.0f;

    #pragma unroll
    for (int c = 0; c < CH; ++c) {
        const float* src = blurred + ((size_t)(b * CH + c)) * NPLANE;
        for (int idx = tlin; idx < (SBY + 2) * (SBX + 2); idx += SBX * SBY) {
            int r = idx / (SBX + 2), cc = idx % (SBX + 2);
            int gy = y0 + r - 1, gx = x0 + cc - 1;
            float v = 0.0f;
            if (gy >= 0 && gy < H && gx >= 0 && gx < W) v = src[gy * W + gx];
            s[r][cc] = v;
        }
        __syncthreads();

        float a00 = s[ty][tx],     a01 = s[ty][tx + 1],     a02 = s[ty][tx + 2];
        float a10 = s[ty + 1][tx],                          a12 = s[ty + 1][tx + 2];
        float a20 = s[ty + 2][tx], a21 = s[ty + 2][tx + 1], a22 = s[ty + 2][tx + 2];

        float gx = (a00 - a02) + 2.0f * (a10 - a12) + (a20 - a22) + shb;
        float gy = (a00 + 2.0f * a01 + a02) - (a20 + 2.0f * a21 + a22) + svb;

        mag += sqrtf(gx * gx + gy * gy);
        sgx += gx;
        sgy += gy;
        __syncthreads();
    }

    const size_t p = (size_t)b * NPLANE + (size_t)(y0 + ty) * W + x0 + tx;
    gm_out[p] = mag;

    float go = atan2f(sgy, sgx) * (180.0f / 3.14159f);
    if (go < 0.0f) go = 360.0f + go;
    go = fmodf(go, 180.0f);
    float orient = rintf(go / 45.0f) * 45.0f;   /* rintf = round half even, matches jnp.round */
    orient_out[p] = orient;

    early_out[p] = (mag < 10.0f) ? 0.0f : mag;
}

/* ------------------------------------------------------------------ */
/* Kernel 3: directional NMS + threshold                              */
/* ------------------------------------------------------------------ */
__global__ __launch_bounds__(256) void nms_kernel(
    const float* __restrict__ gm,
    const float* __restrict__ orient,
    const float* __restrict__ d0b_p,
    const float* __restrict__ d1b_p,
    float* __restrict__ thin,
    float* __restrict__ thresh)
{
    const size_t idx = (size_t)blockIdx.x * blockDim.x + threadIdx.x;
    if (idx >= (size_t)NPIX) return;

    const float d0b = __ldg(d0b_p);
    const float d1b = __ldg(d1b_p);

    const int p = (int)(idx % NPLANE);
    const int i = p / W;
    const int j = p % W;

    const float gmp = gm[idx];
    const float o = orient[idx];
    const int k = (int)(o * (1.0f / 45.0f) + 0.5f);   /* 0..4 exact multiples of 45 */

    /* filter k: center +1 at (0,0), -1 at neighbor offset (cross-correlation) */
    const int DI[5] = { 0, 1, 1, 1, 0 };
    const int DJ[5] = { 1, 1, 0, -1, -1 };
    const float bias = (k < 4) ? d0b : d1b;

    const int ni = i + DI[k];
    const int nj = j + DJ[k];
    float nbv = 0.0f;
    if (ni >= 0 && ni < H && nj >= 0 && nj < W)
        nbv = gm[idx + (size_t)DI[k] * W + DJ[k]];

    const float val = gmp - nbv + bias;
    const float t = (val > 0.0f) ? gmp : 0.0f;
    thin[idx] = t;
    thresh[idx] = (t < 10.0f) ? 0.0f : t;
}

/* ------------------------------------------------------------------ */
extern "C" void kernel_launch(void* const* d_in, const int* in_sizes, int n_in,
                              void* d_out, int out_size)
{
    const float* img = (const float*)d_in[0];
    const float* bh  = (const float*)d_in[1];
    const float* bv  = (const float*)d_in[2];
    const float* shb = (const float*)d_in[3];
    const float* svb = (const float*)d_in[4];
    const float* d0b = (const float*)d_in[5];
    const float* d1b = (const float*)d_in[6];

    float* out     = (float*)d_out;
    float* blurred = out;                          /* 3*NPIX */
    float* gm      = out + (size_t)3 * NPIX;
    float* orient  = gm + NPIX;
    float* thin    = orient + NPIX;
    float* thresh  = thin + NPIX;
    float* early   = thresh + NPIX;

    dim3 g1(W / BX, H / BY, BATCH * CH);
    blur_kernel<<<g1, 256>>>(img, bh, bv, blurred);

    dim3 b2(SBX, SBY);
    dim3 g2(W / SBX, H / SBY, BATCH);
    sobel_kernel<<<g2, b2>>>(blurred, shb, svb, gm, orient, early);

    nms_kernel<<<(NPIX + 255) / 256, 256>>>(gm, orient, d0b, d1b, thin, thresh);

    (void)in_sizes; (void)n_in; (void)out_size;
}